// round 15
// baseline (speedup 1.0000x reference)
#include <cuda_runtime.h>
#include <cuda_fp16.h>
#include <math.h>
#include <stdint.h>

// ---------------------------------------------------------------------------
// MoE top-2/8: fp16 m16n8k16 mma.sync GEMMs (fp32 accum), ldmatrix fragments,
// BK=64, cp.async.cg. CTA tile 128x64, warp tile 32x32, 2-stage pipeline,
// 3 CTAs/SM (24 warps/SM) for latency hiding.
// ---------------------------------------------------------------------------

#define BATCH      8192
#define D_MODEL    1024
#define HIDDEN     4096
#define NUM_CLS    1000
#define N2PAD      1024
#define NUM_EXP    8
#define TOPK       2
#define NPAIR      (BATCH * TOPK)
#define MAX_TILES  136
#define CAP        (MAX_TILES * 128)

#define RTR_BLOCKS (BATCH / 8)
#define T1_BLOCKS  (NUM_EXP * (D_MODEL/64) * (HIDDEN/64))   // 8192
#define T2_BLOCKS  (NUM_EXP * (HIDDEN/64) * (N2PAD/64))     // 8192
#define PREP_BLOCKS (RTR_BLOCKS + T1_BLOCKS + T2_BLOCKS)    // 17408

// ---------------- scratch ---------------------------------------------------
__device__ __half g_h[(size_t)CAP * HIDDEN];
__device__ __half g_xH[(size_t)BATCH * D_MODEL];
__device__ __half g_W1T[(size_t)NUM_EXP * HIDDEN * D_MODEL];    // [e][n][k]
__device__ __half g_W2T[(size_t)NUM_EXP * N2PAD * HIDDEN];      // [e][n][k]
__device__ float g_gates[BATCH * NUM_EXP];
__device__ int   g_topi[BATCH * TOPK];
__device__ int   g_pairExpert[NPAIR];
__device__ float g_pairGate[NPAIR];
__device__ int   g_counts[NUM_EXP];
__device__ int   g_segbase[NUM_EXP + 1];
__device__ int   g_cursor[NUM_EXP];
__device__ int   g_permToken[CAP];
__device__ int   g_permPair[CAP];
__device__ float g_permGate[CAP];
__device__ unsigned g_done;

__device__ __forceinline__ float gelu_exact(float v) {
    return 0.5f * v * (1.0f + erff(v * 0.70710678118654752f));
}
__device__ __forceinline__ uint32_t smem_u32(const void* p) {
    uint32_t a;
    asm("{ .reg .u64 t; cvta.to.shared.u64 t, %1; cvt.u32.u64 %0, t; }" : "=r"(a) : "l"(p));
    return a;
}

#define CPG16(dst, src)        asm volatile("cp.async.cg.shared.global [%0], [%1], 16;" :: "r"(dst), "l"(src))
#define CPG16_SZ(dst, src, sz) asm volatile("cp.async.cg.shared.global [%0], [%1], 16, %2;" :: "r"(dst), "l"(src), "r"(sz))
#define CPA_COMMIT()           asm volatile("cp.async.commit_group;" ::: "memory")
#define CPA_WAIT1()            asm volatile("cp.async.wait_group 1;" ::: "memory")
#define CPA_WAIT0()            asm volatile("cp.async.wait_group 0;" ::: "memory")

__device__ __forceinline__ void mma_f16(float* c, const uint32_t* a, uint32_t b0, uint32_t b1) {
    asm volatile("mma.sync.aligned.m16n8k16.row.col.f32.f16.f16.f32 "
                 "{%0,%1,%2,%3}, {%4,%5,%6,%7}, {%8,%9}, {%0,%1,%2,%3};"
                 : "+f"(c[0]), "+f"(c[1]), "+f"(c[2]), "+f"(c[3])
                 : "r"(a[0]), "r"(a[1]), "r"(a[2]), "r"(a[3]), "r"(b0), "r"(b1));
}
__device__ __forceinline__ void ldsm4(uint32_t* r, uint32_t addr) {
    asm volatile("ldmatrix.sync.aligned.m8n8.x4.shared.b16 {%0,%1,%2,%3}, [%4];"
                 : "=r"(r[0]), "=r"(r[1]), "=r"(r[2]), "=r"(r[3]) : "r"(addr));
}

// ---------------- L1: fused prep (router || transposes) ---------------------
__global__ void prep_all(const float* __restrict__ x,
                         const float* __restrict__ Wg,
                         const float* __restrict__ bg,
                         const float* __restrict__ W1,
                         const float* __restrict__ W2) {
    __shared__ float t[64][65];
    const int bid = blockIdx.x, tid = threadIdx.x;

    if (bid < RTR_BLOCKS) {
        size_t tid0 = (size_t)bid * blockDim.x + tid;
        size_t nthr = (size_t)RTR_BLOCKS * blockDim.x;
        if (tid0 < CAP) { g_permToken[tid0] = -1; g_permPair[tid0] = -1; }
        if (tid0 < NUM_EXP) g_counts[tid0] = 0;

        int gwarp = (int)(tid0 >> 5);
        int lane  = tid & 31;
        const float* xr = x + (size_t)gwarp * D_MODEL;
        float acc[NUM_EXP];
#pragma unroll
        for (int e = 0; e < NUM_EXP; e++) acc[e] = 0.f;
        for (int k0 = lane * 4; k0 < D_MODEL; k0 += 128) {
            float4 xv = *(const float4*)(xr + k0);
            const float* xs = (const float*)&xv;
#pragma unroll
            for (int kk = 0; kk < 4; kk++) {
                const float4* wg = (const float4*)(Wg + (size_t)(k0 + kk) * NUM_EXP);
                float4 w0 = wg[0], w1 = wg[1];
                float xk = xs[kk];
                acc[0] += xk * w0.x; acc[1] += xk * w0.y;
                acc[2] += xk * w0.z; acc[3] += xk * w0.w;
                acc[4] += xk * w1.x; acc[5] += xk * w1.y;
                acc[6] += xk * w1.z; acc[7] += xk * w1.w;
            }
        }
#pragma unroll
        for (int off = 16; off; off >>= 1)
#pragma unroll
            for (int e = 0; e < NUM_EXP; e++)
                acc[e] += __shfl_xor_sync(0xFFFFFFFFu, acc[e], off);
        if (lane == 0) {
            float v[NUM_EXP];
#pragma unroll
            for (int e = 0; e < NUM_EXP; e++) v[e] = acc[e] + bg[e];
            int i1 = 0;
#pragma unroll
            for (int e = 1; e < NUM_EXP; e++) if (v[e] > v[i1]) i1 = e;
            int i2 = -1;
#pragma unroll
            for (int e = 0; e < NUM_EXP; e++)
                if (e != i1 && (i2 < 0 || v[e] > v[i2])) i2 = e;
            float e2 = expf(v[i2] - v[i1]);
            float g1 = 1.f / (1.f + e2), g2 = e2 / (1.f + e2);
#pragma unroll
            for (int e = 0; e < NUM_EXP; e++) g_gates[gwarp * NUM_EXP + e] = 0.f;
            g_gates[gwarp * NUM_EXP + i1] = g1;
            g_gates[gwarp * NUM_EXP + i2] = g2;
            g_topi[gwarp * TOPK + 0] = i1;
            g_topi[gwarp * TOPK + 1] = i2;
            g_pairExpert[gwarp * TOPK + 0] = i1;
            g_pairExpert[gwarp * TOPK + 1] = i2;
            g_pairGate[gwarp * TOPK + 0] = g1;
            g_pairGate[gwarp * TOPK + 1] = g2;
            atomicAdd(&g_counts[i1], 1);
            atomicAdd(&g_counts[i2], 1);
        }

        for (size_t i = tid0; i < (size_t)BATCH * D_MODEL / 4; i += nthr) {
            float4 v = ((const float4*)x)[i];
            ((__half2*)g_xH)[i * 2]     = __floats2half2_rn(v.x, v.y);
            ((__half2*)g_xH)[i * 2 + 1] = __floats2half2_rn(v.z, v.w);
        }

        __syncthreads();
        if (tid == 0) {
            __threadfence();
            unsigned ticket = atomicAdd(&g_done, 1u);
            if (ticket == RTR_BLOCKS - 1) {
                int base = 0;
#pragma unroll
                for (int e = 0; e < NUM_EXP; e++) {
                    g_segbase[e] = base;
                    g_cursor[e]  = base;
                    base += ((g_counts[e] + 127) >> 7) << 7;
                }
                g_segbase[NUM_EXP] = base;
                g_done = 0;
                __threadfence();
            }
        }
        return;
    }

    const int tx = tid & 63, ty4 = tid >> 6;
    int idx = bid - RTR_BLOCKS;
    if (idx < T1_BLOCKS) {
        int e  = idx >> 10;
        int tt = idx & 1023;
        int kB = (tt & 15) * 64;
        int nB = (tt >> 4) * 64;
        const float* src = W1 + (size_t)e * D_MODEL * HIDDEN;
        __half* dst = g_W1T + (size_t)e * HIDDEN * D_MODEL;
#pragma unroll
        for (int i = 0; i < 16; i++) {
            int r = ty4 + i * 4;
            t[r][tx] = src[(size_t)(kB + r) * HIDDEN + nB + tx];
        }
        __syncthreads();
#pragma unroll
        for (int i = 0; i < 16; i++) {
            int r = ty4 + i * 4;
            dst[(size_t)(nB + r) * D_MODEL + kB + tx] = __float2half_rn(t[tx][r]);
        }
    } else {
        idx -= T1_BLOCKS;
        int e  = idx >> 10;
        int tt = idx & 1023;
        int kB = (tt & 63) * 64;
        int nB = (tt >> 6) * 64;
        const float* src = W2 + (size_t)e * HIDDEN * NUM_CLS;
        __half* dst = g_W2T + (size_t)e * N2PAD * HIDDEN;
        int n = nB + tx;
#pragma unroll
        for (int i = 0; i < 16; i++) {
            int r = ty4 + i * 4;
            t[r][tx] = (n < NUM_CLS) ? src[(size_t)(kB + r) * NUM_CLS + n] : 0.f;
        }
        __syncthreads();
#pragma unroll
        for (int i = 0; i < 16; i++) {
            int r = ty4 + i * 4;
            dst[(size_t)(nB + r) * HIDDEN + kB + tx] = __float2half_rn(t[tx][r]);
        }
    }
}

// ---------------- L2: scatter ------------------------------------------------
__global__ void scatter_kernel() {
    int p = blockIdx.x * blockDim.x + threadIdx.x;
    if (p >= NPAIR) return;
    int e = g_pairExpert[p];
    int pos = atomicAdd(&g_cursor[e], 1);
    g_permToken[pos] = p >> 1;
    g_permPair[pos]  = p;
    g_permGate[pos]  = g_pairGate[p];
}

// ---------------- fp16 mma GEMMs --------------------------------------------
// 256 threads (8 warps, 4x2), CTA tile 128x64, warp tile 32x32, BK=64 fp16,
// 2-stage cp.async.cg, 3 CTAs/SM.
#define ROWB      144
#define A_BYTES   (128 * ROWB)                     // 18432
#define B_BYTES   (64 * ROWB)                      // 9216
#define STAGE_B   (A_BYTES + B_BYTES)              // 27648
#define SMEM_TOT  (2 * STAGE_B)                    // 55296

// copy roles: A: thread t -> row t>>1, half-row (t&1)*32 elems, 4 x 16B.
//             B: thread t -> n-row t>>2, quarter-row (t&3)*16 elems, 2 x 16B.
__device__ __forceinline__ void issue_chunk(
    uint32_t aDst, uint32_t bDst,
    const __half* aSrc, uint32_t aSz, const __half* bSrc, int kt)
{
#pragma unroll
    for (int j = 0; j < 4; j++)
        CPG16_SZ(aDst + j * 16, aSrc + kt + j * 8, aSz);
#pragma unroll
    for (int j = 0; j < 2; j++)
        CPG16(bDst + j * 16, bSrc + kt + j * 8);
    CPA_COMMIT();
}

// 32x32 warp tile: 4 ks of (2 a-ldsm + 2 b-ldsm + 8 mma).
__device__ __forceinline__ void mma_tile(uint32_t aAddr, uint32_t bAddr,
                                         float c[2][4][4]) {
#pragma unroll
    for (int ks = 0; ks < 4; ks++) {
        uint32_t a[2][4], b[2][4];
#pragma unroll
        for (int mi = 0; mi < 2; mi++)
            ldsm4(a[mi], aAddr + mi * (16 * ROWB) + ks * 32);
#pragma unroll
        for (int n2 = 0; n2 < 2; n2++)
            ldsm4(b[n2], bAddr + n2 * (16 * ROWB) + ks * 32);
#pragma unroll
        for (int mi = 0; mi < 2; mi++)
#pragma unroll
            for (int n2 = 0; n2 < 2; n2++) {
                mma_f16(c[mi][2 * n2],     a[mi], b[n2][0], b[n2][1]);
                mma_f16(c[mi][2 * n2 + 1], a[mi], b[n2][2], b[n2][3]);
            }
    }
}

// 2-stage pipeline (R11-proven structure).
__device__ __forceinline__ void gemm_mainloop(
    uint32_t aDst, uint32_t bDst,
    const __half* aSrc, uint32_t aSz, const __half* bSrc, int NIT,
    uint32_t aAddr, uint32_t bAddr, float c[2][4][4])
{
    issue_chunk(aDst, bDst, aSrc, aSz, bSrc, 0);
    for (int it = 0; it < NIT; ++it) {
        if (it + 1 < NIT) {
            int nb = (it + 1) & 1;
            issue_chunk(aDst + nb * STAGE_B, bDst + nb * STAGE_B,
                        aSrc, aSz, bSrc, (it + 1) * 64);
            CPA_WAIT1();
        } else {
            CPA_WAIT0();
        }
        __syncthreads();
        int buf = it & 1;
        mma_tile(aAddr + buf * STAGE_B, bAddr + buf * STAGE_B, c);
        __syncthreads();
    }
}

__global__ __launch_bounds__(256, 3)
void gemm1_mma(const float* __restrict__ b1) {
    extern __shared__ __align__(16) char smem[];
    const int tid = threadIdx.x, wid = tid >> 5, lane = tid & 31;
    const int rowBase = blockIdx.x * 128, nBase = blockIdx.y * 64;
    if (rowBase >= g_segbase[NUM_EXP]) return;
    int expert = 0;
#pragma unroll
    for (int i = 1; i < NUM_EXP; i++) if (g_segbase[i] <= rowBase) expert = i;

    uint32_t sb = smem_u32(smem);
    const int cr = tid >> 1, co = (tid & 1) * 32;
    uint32_t aDst = sb + cr * ROWB + co * 2;
    const int br = tid >> 2, bq = (tid & 3) * 16;
    uint32_t bDst = sb + A_BYTES + br * ROWB + bq * 2;

    const int tok = g_permToken[rowBase + cr];
    const __half* aSrc = g_xH + (size_t)(tok < 0 ? 0 : tok) * D_MODEL + co;
    uint32_t aSz = tok < 0 ? 0u : 16u;
    const __half* bSrc = g_W1T + (size_t)expert * HIDDEN * D_MODEL
                       + (size_t)(nBase + br) * D_MODEL + bq;

    const int gid = lane >> 2, tig = lane & 3;
    const int wr = (wid & 3) * 32, wc = (wid >> 2) * 32;
    const int g8 = lane >> 3, r8 = lane & 7;
    uint32_t aAddr = sb + (wr + (g8 & 1) * 8 + r8) * ROWB + (g8 >> 1) * 16;
    uint32_t bAddr = sb + A_BYTES + (wc + (g8 >> 1) * 8 + r8) * ROWB + (g8 & 1) * 16;

    float c[2][4][4];
#pragma unroll
    for (int mi = 0; mi < 2; mi++)
#pragma unroll
        for (int ni = 0; ni < 4; ni++)
#pragma unroll
            for (int q = 0; q < 4; q++) c[mi][ni][q] = 0.f;

    gemm_mainloop(aDst, bDst, aSrc, aSz, bSrc, D_MODEL / 64, aAddr, bAddr, c);

    const float* bb = b1 + (size_t)expert * HIDDEN + nBase;
#pragma unroll
    for (int mi = 0; mi < 2; mi++) {
        int r0 = rowBase + wr + mi * 16 + gid;
#pragma unroll
        for (int ni = 0; ni < 4; ni++) {
            int col = wc + ni * 8 + tig * 2;
            float bias0 = __ldg(bb + col), bias1 = __ldg(bb + col + 1);
            __half2 v0 = __floats2half2_rn(gelu_exact(c[mi][ni][0] + bias0),
                                           gelu_exact(c[mi][ni][1] + bias1));
            __half2 v1 = __floats2half2_rn(gelu_exact(c[mi][ni][2] + bias0),
                                           gelu_exact(c[mi][ni][3] + bias1));
            *(__half2*)(g_h + (size_t)r0 * HIDDEN + nBase + col) = v0;
            *(__half2*)(g_h + (size_t)(r0 + 8) * HIDDEN + nBase + col) = v1;
        }
    }
}

// grid = (nTiles fast, rowTiles) for g_h L2 reuse.
__global__ __launch_bounds__(256, 3)
void gemm2_mma(const float* __restrict__ b2, float* __restrict__ out) {
    extern __shared__ __align__(16) char smem[];
    const int tid = threadIdx.x, wid = tid >> 5, lane = tid & 31;
    const int rowBase = blockIdx.y * 128, nBase = blockIdx.x * 64;
    if (rowBase >= g_segbase[NUM_EXP]) return;
    int expert = 0;
#pragma unroll
    for (int i = 1; i < NUM_EXP; i++) if (g_segbase[i] <= rowBase) expert = i;

    uint32_t sb = smem_u32(smem);
    const int cr = tid >> 1, co = (tid & 1) * 32;
    uint32_t aDst = sb + cr * ROWB + co * 2;
    const int br = tid >> 2, bq = (tid & 3) * 16;
    uint32_t bDst = sb + A_BYTES + br * ROWB + bq * 2;

    const __half* aSrc = g_h + (size_t)(rowBase + cr) * HIDDEN + co;
    const __half* bSrc = g_W2T + (size_t)expert * N2PAD * HIDDEN
                       + (size_t)(nBase + br) * HIDDEN + bq;

    const int gid = lane >> 2, tig = lane & 3;
    const int wr = (wid & 3) * 32, wc = (wid >> 2) * 32;
    const int g8 = lane >> 3, r8 = lane & 7;
    uint32_t aAddr = sb + (wr + (g8 & 1) * 8 + r8) * ROWB + (g8 >> 1) * 16;
    uint32_t bAddr = sb + A_BYTES + (wc + (g8 >> 1) * 8 + r8) * ROWB + (g8 & 1) * 16;

    float c[2][4][4];
#pragma unroll
    for (int mi = 0; mi < 2; mi++)
#pragma unroll
        for (int ni = 0; ni < 4; ni++)
#pragma unroll
            for (int q = 0; q < 4; q++) c[mi][ni][q] = 0.f;

    gemm_mainloop(aDst, bDst, aSrc, 16u, bSrc, HIDDEN / 64, aAddr, bAddr, c);

    const float* bb = b2 + (size_t)expert * NUM_CLS;
#pragma unroll
    for (int mi = 0; mi < 2; mi++) {
        int r0 = rowBase + wr + mi * 16 + gid;
#pragma unroll
        for (int half = 0; half < 2; half++) {
            int r = r0 + half * 8;
            int pair = g_permPair[r];
            if (pair < 0) continue;
            float gate = g_permGate[r];
            float* orow = out + (size_t)(pair >> 1) * NUM_CLS;
#pragma unroll
            for (int ni = 0; ni < 4; ni++) {
                int col = nBase + wc + ni * 8 + tig * 2;
                if (col < NUM_CLS)
                    atomicAdd(orow + col, gate * (c[mi][ni][half * 2 + 0] + __ldg(bb + col)));
                if (col + 1 < NUM_CLS)
                    atomicAdd(orow + col + 1, gate * (c[mi][ni][half * 2 + 1] + __ldg(bb + col + 1)));
            }
        }
    }
}

// ---------------- tail -------------------------------------------------------
__global__ void tail_kernel(float* __restrict__ out, int out_size) {
    int i = blockIdx.x * blockDim.x + threadIdx.x;
    const int OUT0 = BATCH * NUM_CLS;
    if (out_size >= OUT0 + BATCH * NUM_EXP) {
        if (i < BATCH * NUM_EXP)
            out[OUT0 + i] = g_gates[i];
        if (out_size >= OUT0 + BATCH * NUM_EXP + BATCH * TOPK && i < BATCH * TOPK)
            out[OUT0 + BATCH * NUM_EXP + i] = (float)g_topi[i];
    }
}

// ---------------------------------------------------------------------------
extern "C" void kernel_launch(void* const* d_in, const int* in_sizes, int n_in,
                              void* d_out, int out_size) {
    const float* x  = (const float*)d_in[0];
    const float* Wg = (const float*)d_in[1];
    const float* bg = (const float*)d_in[2];
    const float* W1 = (const float*)d_in[3];
    const float* b1 = (const float*)d_in[4];
    const float* W2 = (const float*)d_in[5];
    const float* b2 = (const float*)d_in[6];
    float* out = (float*)d_out;

    cudaFuncSetAttribute(gemm1_mma, cudaFuncAttributeMaxDynamicSharedMemorySize, SMEM_TOT);
    cudaFuncSetAttribute(gemm2_mma, cudaFuncAttributeMaxDynamicSharedMemorySize, SMEM_TOT);

    // ncu profiles launch index 4 -> gemm2_mma.
    cudaMemsetAsync(d_out, 0, (size_t)out_size * sizeof(float));             // 0
    prep_all<<<PREP_BLOCKS, 256>>>(x, Wg, bg, W1, W2);                       // 1
    scatter_kernel<<<(NPAIR + 255) / 256, 256>>>();                          // 2
    gemm1_mma<<<dim3(MAX_TILES, HIDDEN / 64), 256, SMEM_TOT>>>(b1);          // 3
    gemm2_mma<<<dim3(N2PAD / 64, MAX_TILES), 256, SMEM_TOT>>>(b2, out);      // 4 <- ncu
    tail_kernel<<<(BATCH * NUM_EXP + 255) / 256, 256>>>(out, out_size);      // 5
}

// round 16
// speedup vs baseline: 1.0878x; 1.0878x over previous
#include <cuda_runtime.h>
#include <cuda_fp16.h>
#include <math.h>
#include <stdint.h>

// ---------------------------------------------------------------------------
// MoE top-2/8: fp16 m16n8k16 mma.sync GEMMs (fp32 accum), ldmatrix fragments,
// BK=64, cp.async.cg, 3-stage single-sync pipeline, 256-thread CTAs
// (8 warps x 64x32, 16 warps/SM). Scatter fused into prep ticket-winner.
// ---------------------------------------------------------------------------

#define BATCH      8192
#define D_MODEL    1024
#define HIDDEN     4096
#define NUM_CLS    1000
#define N2PAD      1024
#define NUM_EXP    8
#define TOPK       2
#define NPAIR      (BATCH * TOPK)
#define MAX_TILES  136
#define CAP        (MAX_TILES * 128)

#define RTR_BLOCKS (BATCH / 8)
#define T1_BLOCKS  (NUM_EXP * (D_MODEL/64) * (HIDDEN/64))   // 8192
#define T2_BLOCKS  (NUM_EXP * (HIDDEN/64) * (N2PAD/64))     // 8192
#define PREP_BLOCKS (RTR_BLOCKS + T1_BLOCKS + T2_BLOCKS)    // 17408

// ---------------- scratch ---------------------------------------------------
__device__ __half g_h[(size_t)CAP * HIDDEN];
__device__ __half g_xH[(size_t)BATCH * D_MODEL];
__device__ __half g_W1T[(size_t)NUM_EXP * HIDDEN * D_MODEL];    // [e][n][k]
__device__ __half g_W2T[(size_t)NUM_EXP * N2PAD * HIDDEN];      // [e][n][k]
__device__ float g_gates[BATCH * NUM_EXP];
__device__ int   g_topi[BATCH * TOPK];
__device__ int   g_pairExpert[NPAIR];
__device__ float g_pairGate[NPAIR];
__device__ int   g_counts[NUM_EXP];
__device__ int   g_segbase[NUM_EXP + 1];
__device__ int   g_cursor[NUM_EXP];
__device__ int   g_permToken[CAP];
__device__ int   g_permPair[CAP];
__device__ float g_permGate[CAP];
__device__ unsigned g_done;

__device__ __forceinline__ float gelu_exact(float v) {
    return 0.5f * v * (1.0f + erff(v * 0.70710678118654752f));
}
__device__ __forceinline__ uint32_t smem_u32(const void* p) {
    uint32_t a;
    asm("{ .reg .u64 t; cvta.to.shared.u64 t, %1; cvt.u32.u64 %0, t; }" : "=r"(a) : "l"(p));
    return a;
}

#define CPG16(dst, src)        asm volatile("cp.async.cg.shared.global [%0], [%1], 16;" :: "r"(dst), "l"(src))
#define CPG16_SZ(dst, src, sz) asm volatile("cp.async.cg.shared.global [%0], [%1], 16, %2;" :: "r"(dst), "l"(src), "r"(sz))
#define CPA_COMMIT()           asm volatile("cp.async.commit_group;" ::: "memory")
#define CPA_WAIT1()            asm volatile("cp.async.wait_group 1;" ::: "memory")
#define CPA_WAIT0()            asm volatile("cp.async.wait_group 0;" ::: "memory")

__device__ __forceinline__ void mma_f16(float* c, const uint32_t* a, uint32_t b0, uint32_t b1) {
    asm volatile("mma.sync.aligned.m16n8k16.row.col.f32.f16.f16.f32 "
                 "{%0,%1,%2,%3}, {%4,%5,%6,%7}, {%8,%9}, {%0,%1,%2,%3};"
                 : "+f"(c[0]), "+f"(c[1]), "+f"(c[2]), "+f"(c[3])
                 : "r"(a[0]), "r"(a[1]), "r"(a[2]), "r"(a[3]), "r"(b0), "r"(b1));
}
__device__ __forceinline__ void ldsm4(uint32_t* r, uint32_t addr) {
    asm volatile("ldmatrix.sync.aligned.m8n8.x4.shared.b16 {%0,%1,%2,%3}, [%4];"
                 : "=r"(r[0]), "=r"(r[1]), "=r"(r[2]), "=r"(r[3]) : "r"(addr));
}

// ---------------- L1: fused prep (router || transposes, + fused scatter) ----
__global__ void prep_all(const float* __restrict__ x,
                         const float* __restrict__ Wg,
                         const float* __restrict__ bg,
                         const float* __restrict__ W1,
                         const float* __restrict__ W2) {
    __shared__ float t[64][65];
    __shared__ int s_flag;
    const int bid = blockIdx.x, tid = threadIdx.x;

    if (bid < RTR_BLOCKS) {
        if (tid == 0) s_flag = 0;
        size_t tid0 = (size_t)bid * blockDim.x + tid;
        size_t nthr = (size_t)RTR_BLOCKS * blockDim.x;
        if (tid0 < CAP) { g_permToken[tid0] = -1; g_permPair[tid0] = -1; }
        if (tid0 < NUM_EXP) g_counts[tid0] = 0;

        int gwarp = (int)(tid0 >> 5);
        int lane  = tid & 31;
        const float* xr = x + (size_t)gwarp * D_MODEL;
        float acc[NUM_EXP];
#pragma unroll
        for (int e = 0; e < NUM_EXP; e++) acc[e] = 0.f;
        for (int k0 = lane * 4; k0 < D_MODEL; k0 += 128) {
            float4 xv = *(const float4*)(xr + k0);
            const float* xs = (const float*)&xv;
#pragma unroll
            for (int kk = 0; kk < 4; kk++) {
                const float4* wg = (const float4*)(Wg + (size_t)(k0 + kk) * NUM_EXP);
                float4 w0 = wg[0], w1 = wg[1];
                float xk = xs[kk];
                acc[0] += xk * w0.x; acc[1] += xk * w0.y;
                acc[2] += xk * w0.z; acc[3] += xk * w0.w;
                acc[4] += xk * w1.x; acc[5] += xk * w1.y;
                acc[6] += xk * w1.z; acc[7] += xk * w1.w;
            }
        }
#pragma unroll
        for (int off = 16; off; off >>= 1)
#pragma unroll
            for (int e = 0; e < NUM_EXP; e++)
                acc[e] += __shfl_xor_sync(0xFFFFFFFFu, acc[e], off);
        if (lane == 0) {
            float v[NUM_EXP];
#pragma unroll
            for (int e = 0; e < NUM_EXP; e++) v[e] = acc[e] + bg[e];
            int i1 = 0;
#pragma unroll
            for (int e = 1; e < NUM_EXP; e++) if (v[e] > v[i1]) i1 = e;
            int i2 = -1;
#pragma unroll
            for (int e = 0; e < NUM_EXP; e++)
                if (e != i1 && (i2 < 0 || v[e] > v[i2])) i2 = e;
            float e2 = expf(v[i2] - v[i1]);
            float g1 = 1.f / (1.f + e2), g2 = e2 / (1.f + e2);
#pragma unroll
            for (int e = 0; e < NUM_EXP; e++) g_gates[gwarp * NUM_EXP + e] = 0.f;
            g_gates[gwarp * NUM_EXP + i1] = g1;
            g_gates[gwarp * NUM_EXP + i2] = g2;
            g_topi[gwarp * TOPK + 0] = i1;
            g_topi[gwarp * TOPK + 1] = i2;
            g_pairExpert[gwarp * TOPK + 0] = i1;
            g_pairExpert[gwarp * TOPK + 1] = i2;
            g_pairGate[gwarp * TOPK + 0] = g1;
            g_pairGate[gwarp * TOPK + 1] = g2;
            atomicAdd(&g_counts[i1], 1);
            atomicAdd(&g_counts[i2], 1);
        }

        for (size_t i = tid0; i < (size_t)BATCH * D_MODEL / 4; i += nthr) {
            float4 v = ((const float4*)x)[i];
            ((__half2*)g_xH)[i * 2]     = __floats2half2_rn(v.x, v.y);
            ((__half2*)g_xH)[i * 2 + 1] = __floats2half2_rn(v.z, v.w);
        }

        __syncthreads();
        if (tid == 0) {
            __threadfence();
            unsigned ticket = atomicAdd(&g_done, 1u);
            if (ticket == RTR_BLOCKS - 1) {          // all router blocks done
                int base = 0;
#pragma unroll
                for (int e = 0; e < NUM_EXP; e++) {
                    g_segbase[e] = base;
                    g_cursor[e]  = base;
                    base += ((g_counts[e] + 127) >> 7) << 7;
                }
                g_segbase[NUM_EXP] = base;
                g_done = 0;
                __threadfence();
                s_flag = 1;
            }
        }
        __syncthreads();
        if (s_flag) {
            // winner block scatters all pairs (overlaps remaining transposes)
            for (int p = tid; p < NPAIR; p += 256) {
                int e = g_pairExpert[p];
                int pos = atomicAdd(&g_cursor[e], 1);
                g_permToken[pos] = p >> 1;
                g_permPair[pos]  = p;
                g_permGate[pos]  = g_pairGate[p];
            }
            __threadfence();
        }
        return;
    }

    const int tx = tid & 63, ty4 = tid >> 6;
    int idx = bid - RTR_BLOCKS;
    if (idx < T1_BLOCKS) {
        int e  = idx >> 10;
        int tt = idx & 1023;
        int kB = (tt & 15) * 64;
        int nB = (tt >> 4) * 64;
        const float* src = W1 + (size_t)e * D_MODEL * HIDDEN;
        __half* dst = g_W1T + (size_t)e * HIDDEN * D_MODEL;
#pragma unroll
        for (int i = 0; i < 16; i++) {
            int r = ty4 + i * 4;
            t[r][tx] = src[(size_t)(kB + r) * HIDDEN + nB + tx];
        }
        __syncthreads();
#pragma unroll
        for (int i = 0; i < 16; i++) {
            int r = ty4 + i * 4;
            dst[(size_t)(nB + r) * D_MODEL + kB + tx] = __float2half_rn(t[tx][r]);
        }
    } else {
        idx -= T1_BLOCKS;
        int e  = idx >> 10;
        int tt = idx & 1023;
        int kB = (tt & 63) * 64;
        int nB = (tt >> 6) * 64;
        const float* src = W2 + (size_t)e * HIDDEN * NUM_CLS;
        __half* dst = g_W2T + (size_t)e * N2PAD * HIDDEN;
        int n = nB + tx;
#pragma unroll
        for (int i = 0; i < 16; i++) {
            int r = ty4 + i * 4;
            t[r][tx] = (n < NUM_CLS) ? src[(size_t)(kB + r) * NUM_CLS + n] : 0.f;
        }
        __syncthreads();
#pragma unroll
        for (int i = 0; i < 16; i++) {
            int r = ty4 + i * 4;
            dst[(size_t)(nB + r) * HIDDEN + kB + tx] = __float2half_rn(t[tx][r]);
        }
    }
}

// ---------------- fp16 mma GEMMs (R14-proven) -------------------------------
#define ROWB      144
#define A_BYTES   (128 * ROWB)
#define B_BYTES   (128 * ROWB)
#define STAGE_B   (A_BYTES + B_BYTES)
#define NSTAGE    3
#define SMEM_TOT  (NSTAGE * STAGE_B)               // 110592

__device__ __forceinline__ void issue_chunk(
    uint32_t aDst, uint32_t bDst,
    const __half* aSrc, uint32_t aSz, const __half* bSrc, int kt)
{
#pragma unroll
    for (int j = 0; j < 4; j++)
        CPG16_SZ(aDst + j * 16, aSrc + kt + j * 8, aSz);
#pragma unroll
    for (int j = 0; j < 4; j++)
        CPG16(bDst + j * 16, bSrc + kt + j * 8);
    CPA_COMMIT();
}

__device__ __forceinline__ void mma_tile(uint32_t aAddr, uint32_t bAddr,
                                         float c[4][4][4]) {
#pragma unroll
    for (int ks = 0; ks < 4; ks++) {
        uint32_t a[4][4], b[2][4];
#pragma unroll
        for (int mi = 0; mi < 4; mi++)
            ldsm4(a[mi], aAddr + mi * (16 * ROWB) + ks * 32);
#pragma unroll
        for (int n2 = 0; n2 < 2; n2++)
            ldsm4(b[n2], bAddr + n2 * (16 * ROWB) + ks * 32);
#pragma unroll
        for (int mi = 0; mi < 4; mi++)
#pragma unroll
            for (int n2 = 0; n2 < 2; n2++) {
                mma_f16(c[mi][2 * n2],     a[mi], b[n2][0], b[n2][1]);
                mma_f16(c[mi][2 * n2 + 1], a[mi], b[n2][2], b[n2][3]);
            }
    }
}

__device__ __forceinline__ void gemm_mainloop(
    uint32_t aDst, uint32_t bDst,
    const __half* aSrc, uint32_t aSz, const __half* bSrc, int NIT,
    uint32_t aAddr, uint32_t bAddr, float c[4][4][4])
{
    issue_chunk(aDst, bDst, aSrc, aSz, bSrc, 0);
    issue_chunk(aDst + STAGE_B, bDst + STAGE_B, aSrc, aSz, bSrc, 64);
    int buf = 0, nxt = 2;
    for (int it = 0; it < NIT; ++it) {
        if (it + 1 < NIT) CPA_WAIT1(); else CPA_WAIT0();
        __syncthreads();
        if (it + 2 < NIT)
            issue_chunk(aDst + nxt * STAGE_B, bDst + nxt * STAGE_B,
                        aSrc, aSz, bSrc, (it + 2) * 64);
        mma_tile(aAddr + buf * STAGE_B, bAddr + buf * STAGE_B, c);
        buf = (buf == NSTAGE - 1) ? 0 : buf + 1;
        nxt = (nxt == NSTAGE - 1) ? 0 : nxt + 1;
    }
}

__global__ __launch_bounds__(256, 2)
void gemm1_mma(const float* __restrict__ b1) {
    extern __shared__ __align__(16) char smem[];
    const int tid = threadIdx.x, wid = tid >> 5, lane = tid & 31;
    const int rowBase = blockIdx.x * 128, nBase = blockIdx.y * 128;
    if (rowBase >= g_segbase[NUM_EXP]) return;
    int expert = 0;
#pragma unroll
    for (int i = 1; i < NUM_EXP; i++) if (g_segbase[i] <= rowBase) expert = i;

    uint32_t sb = smem_u32(smem);
    const int cr = tid >> 1, co = (tid & 1) * 32;
    uint32_t aDst = sb + cr * ROWB + co * 2;
    uint32_t bDst = sb + A_BYTES + cr * ROWB + co * 2;

    const int tok = g_permToken[rowBase + cr];
    const __half* aSrc = g_xH + (size_t)(tok < 0 ? 0 : tok) * D_MODEL + co;
    uint32_t aSz = tok < 0 ? 0u : 16u;
    const __half* bSrc = g_W1T + (size_t)expert * HIDDEN * D_MODEL
                       + (size_t)(nBase + cr) * D_MODEL + co;

    const int gid = lane >> 2, tig = lane & 3;
    const int wr = (wid >> 2) * 64, wc = (wid & 3) * 32;
    const int g8 = lane >> 3, r8 = lane & 7;
    uint32_t aAddr = sb + (wr + (g8 & 1) * 8 + r8) * ROWB + (g8 >> 1) * 16;
    uint32_t bAddr = sb + A_BYTES + (wc + (g8 >> 1) * 8 + r8) * ROWB + (g8 & 1) * 16;

    float c[4][4][4];
#pragma unroll
    for (int mi = 0; mi < 4; mi++)
#pragma unroll
        for (int ni = 0; ni < 4; ni++)
#pragma unroll
            for (int q = 0; q < 4; q++) c[mi][ni][q] = 0.f;

    gemm_mainloop(aDst, bDst, aSrc, aSz, bSrc, D_MODEL / 64, aAddr, bAddr, c);

    const float* bb = b1 + (size_t)expert * HIDDEN + nBase;
#pragma unroll
    for (int mi = 0; mi < 4; mi++) {
        int r0 = rowBase + wr + mi * 16 + gid;
#pragma unroll
        for (int ni = 0; ni < 4; ni++) {
            int col = wc + ni * 8 + tig * 2;
            float bias0 = __ldg(bb + col), bias1 = __ldg(bb + col + 1);
            __half2 v0 = __floats2half2_rn(gelu_exact(c[mi][ni][0] + bias0),
                                           gelu_exact(c[mi][ni][1] + bias1));
            __half2 v1 = __floats2half2_rn(gelu_exact(c[mi][ni][2] + bias0),
                                           gelu_exact(c[mi][ni][3] + bias1));
            *(__half2*)(g_h + (size_t)r0 * HIDDEN + nBase + col) = v0;
            *(__half2*)(g_h + (size_t)(r0 + 8) * HIDDEN + nBase + col) = v1;
        }
    }
}

// grid = (nTiles fast, rowTiles) for g_h L2 reuse.
__global__ __launch_bounds__(256, 2)
void gemm2_mma(const float* __restrict__ b2, float* __restrict__ out) {
    extern __shared__ __align__(16) char smem[];
    const int tid = threadIdx.x, wid = tid >> 5, lane = tid & 31;
    const int rowBase = blockIdx.y * 128, nBase = blockIdx.x * 128;
    if (rowBase >= g_segbase[NUM_EXP]) return;
    int expert = 0;
#pragma unroll
    for (int i = 1; i < NUM_EXP; i++) if (g_segbase[i] <= rowBase) expert = i;

    uint32_t sb = smem_u32(smem);
    const int cr = tid >> 1, co = (tid & 1) * 32;
    uint32_t aDst = sb + cr * ROWB + co * 2;
    uint32_t bDst = sb + A_BYTES + cr * ROWB + co * 2;

    const __half* aSrc = g_h + (size_t)(rowBase + cr) * HIDDEN + co;
    const __half* bSrc = g_W2T + (size_t)expert * N2PAD * HIDDEN
                       + (size_t)(nBase + cr) * HIDDEN + co;

    const int gid = lane >> 2, tig = lane & 3;
    const int wr = (wid >> 2) * 64, wc = (wid & 3) * 32;
    const int g8 = lane >> 3, r8 = lane & 7;
    uint32_t aAddr = sb + (wr + (g8 & 1) * 8 + r8) * ROWB + (g8 >> 1) * 16;
    uint32_t bAddr = sb + A_BYTES + (wc + (g8 >> 1) * 8 + r8) * ROWB + (g8 & 1) * 16;

    float c[4][4][4];
#pragma unroll
    for (int mi = 0; mi < 4; mi++)
#pragma unroll
        for (int ni = 0; ni < 4; ni++)
#pragma unroll
            for (int q = 0; q < 4; q++) c[mi][ni][q] = 0.f;

    gemm_mainloop(aDst, bDst, aSrc, 16u, bSrc, HIDDEN / 64, aAddr, bAddr, c);

    const float* bb = b2 + (size_t)expert * NUM_CLS;
#pragma unroll
    for (int mi = 0; mi < 4; mi++) {
        int r0 = rowBase + wr + mi * 16 + gid;
#pragma unroll
        for (int half = 0; half < 2; half++) {
            int r = r0 + half * 8;
            int pair = g_permPair[r];
            if (pair < 0) continue;
            float gate = g_permGate[r];
            float* orow = out + (size_t)(pair >> 1) * NUM_CLS;
#pragma unroll
            for (int ni = 0; ni < 4; ni++) {
                int col = nBase + wc + ni * 8 + tig * 2;
                if (col < NUM_CLS)
                    atomicAdd(orow + col, gate * (c[mi][ni][half * 2 + 0] + __ldg(bb + col)));
                if (col + 1 < NUM_CLS)
                    atomicAdd(orow + col + 1, gate * (c[mi][ni][half * 2 + 1] + __ldg(bb + col + 1)));
            }
        }
    }
}

// ---------------- tail (runs BEFORE gemm2: disjoint out ranges) --------------
__global__ void tail_kernel(float* __restrict__ out, int out_size) {
    int i = blockIdx.x * blockDim.x + threadIdx.x;
    const int OUT0 = BATCH * NUM_CLS;
    if (out_size >= OUT0 + BATCH * NUM_EXP) {
        if (i < BATCH * NUM_EXP)
            out[OUT0 + i] = g_gates[i];
        if (out_size >= OUT0 + BATCH * NUM_EXP + BATCH * TOPK && i < BATCH * TOPK)
            out[OUT0 + BATCH * NUM_EXP + i] = (float)g_topi[i];
    }
}

// ---------------------------------------------------------------------------
extern "C" void kernel_launch(void* const* d_in, const int* in_sizes, int n_in,
                              void* d_out, int out_size) {
    const float* x  = (const float*)d_in[0];
    const float* Wg = (const float*)d_in[1];
    const float* bg = (const float*)d_in[2];
    const float* W1 = (const float*)d_in[3];
    const float* b1 = (const float*)d_in[4];
    const float* W2 = (const float*)d_in[5];
    const float* b2 = (const float*)d_in[6];
    float* out = (float*)d_out;

    cudaFuncSetAttribute(gemm1_mma, cudaFuncAttributeMaxDynamicSharedMemorySize, SMEM_TOT);
    cudaFuncSetAttribute(gemm2_mma, cudaFuncAttributeMaxDynamicSharedMemorySize, SMEM_TOT);

    // ncu profiles launch index 4 -> gemm2_mma.
    cudaMemsetAsync(d_out, 0, (size_t)out_size * sizeof(float));             // 0
    prep_all<<<PREP_BLOCKS, 256>>>(x, Wg, bg, W1, W2);                       // 1 (scatter fused)
    gemm1_mma<<<dim3(MAX_TILES, HIDDEN / 128), 256, SMEM_TOT>>>(b1);         // 2
    tail_kernel<<<(BATCH * NUM_EXP + 255) / 256, 256>>>(out, out_size);      // 3
    gemm2_mma<<<dim3(N2PAD / 128, MAX_TILES), 256, SMEM_TOT>>>(b2, out);     // 4 <- ncu
}

// round 17
// speedup vs baseline: 1.1037x; 1.0145x over previous
#include <cuda_runtime.h>
#include <cuda_fp16.h>
#include <math.h>
#include <stdint.h>

// ---------------------------------------------------------------------------
// MoE top-2/8: fp16 m16n8k16 mma.sync GEMMs (fp32 accum), ldmatrix fragments,
// BK=64, cp.async.cg, 3-stage single-sync pipeline, 256-thread CTAs
// (8 warps x 64x32, 16 warps/SM). W2 transpose fused into gemm1 launch.
// ---------------------------------------------------------------------------

#define BATCH      8192
#define D_MODEL    1024
#define HIDDEN     4096
#define NUM_CLS    1000
#define N2PAD      1024
#define NUM_EXP    8
#define TOPK       2
#define NPAIR      (BATCH * TOPK)
#define MAX_TILES  136
#define CAP        (MAX_TILES * 128)

#define RTR_BLOCKS (BATCH / 8)                              // 1024
#define T1_BLOCKS  (NUM_EXP * (D_MODEL/64) * (HIDDEN/64))   // 8192
#define T2_BLOCKS  (NUM_EXP * (HIDDEN/64) * (N2PAD/64))     // 8192
#define PREP_BLOCKS (RTR_BLOCKS + T1_BLOCKS)                // 9216
#define G1_BLOCKS  (MAX_TILES * (HIDDEN / 128))             // 4352

// ---------------- scratch ---------------------------------------------------
__device__ __half g_h[(size_t)CAP * HIDDEN];
__device__ __half g_xH[(size_t)BATCH * D_MODEL];
__device__ __half g_W1T[(size_t)NUM_EXP * HIDDEN * D_MODEL];    // [e][n][k]
__device__ __half g_W2T[(size_t)NUM_EXP * N2PAD * HIDDEN];      // [e][n][k]
__device__ float g_gates[BATCH * NUM_EXP];
__device__ int   g_topi[BATCH * TOPK];
__device__ int   g_pairExpert[NPAIR];
__device__ float g_pairGate[NPAIR];
__device__ int   g_counts[NUM_EXP];
__device__ int   g_segbase[NUM_EXP + 1];
__device__ int   g_cursor[NUM_EXP];
__device__ int   g_permToken[CAP];
__device__ int   g_permPair[CAP];
__device__ float g_permGate[CAP];
__device__ unsigned g_done;

__device__ __forceinline__ float gelu_exact(float v) {
    return 0.5f * v * (1.0f + erff(v * 0.70710678118654752f));
}
__device__ __forceinline__ uint32_t smem_u32(const void* p) {
    uint32_t a;
    asm("{ .reg .u64 t; cvta.to.shared.u64 t, %1; cvt.u32.u64 %0, t; }" : "=r"(a) : "l"(p));
    return a;
}

#define CPG16(dst, src)        asm volatile("cp.async.cg.shared.global [%0], [%1], 16;" :: "r"(dst), "l"(src))
#define CPG16_SZ(dst, src, sz) asm volatile("cp.async.cg.shared.global [%0], [%1], 16, %2;" :: "r"(dst), "l"(src), "r"(sz))
#define CPA_COMMIT()           asm volatile("cp.async.commit_group;" ::: "memory")
#define CPA_WAIT1()            asm volatile("cp.async.wait_group 1;" ::: "memory")
#define CPA_WAIT0()            asm volatile("cp.async.wait_group 0;" ::: "memory")

__device__ __forceinline__ void mma_f16(float* c, const uint32_t* a, uint32_t b0, uint32_t b1) {
    asm volatile("mma.sync.aligned.m16n8k16.row.col.f32.f16.f16.f32 "
                 "{%0,%1,%2,%3}, {%4,%5,%6,%7}, {%8,%9}, {%0,%1,%2,%3};"
                 : "+f"(c[0]), "+f"(c[1]), "+f"(c[2]), "+f"(c[3])
                 : "r"(a[0]), "r"(a[1]), "r"(a[2]), "r"(a[3]), "r"(b0), "r"(b1));
}
__device__ __forceinline__ void ldsm4(uint32_t* r, uint32_t addr) {
    asm volatile("ldmatrix.sync.aligned.m8n8.x4.shared.b16 {%0,%1,%2,%3}, [%4];"
                 : "=r"(r[0]), "=r"(r[1]), "=r"(r[2]), "=r"(r[3]) : "r"(addr));
}

// ---------------- L1: prep = router + x->fp16 + W1 transpose ----------------
__global__ void prep_all(const float* __restrict__ x,
                         const float* __restrict__ Wg,
                         const float* __restrict__ bg,
                         const float* __restrict__ W1) {
    __shared__ float t[64][65];
    const int bid = blockIdx.x, tid = threadIdx.x;

    if (bid < RTR_BLOCKS) {
        size_t tid0 = (size_t)bid * blockDim.x + tid;
        size_t nthr = (size_t)RTR_BLOCKS * blockDim.x;
        if (tid0 < CAP) { g_permToken[tid0] = -1; g_permPair[tid0] = -1; }
        if (tid0 < NUM_EXP) g_counts[tid0] = 0;

        int gwarp = (int)(tid0 >> 5);
        int lane  = tid & 31;
        const float* xr = x + (size_t)gwarp * D_MODEL;
        float acc[NUM_EXP];
#pragma unroll
        for (int e = 0; e < NUM_EXP; e++) acc[e] = 0.f;
        for (int k0 = lane * 4; k0 < D_MODEL; k0 += 128) {
            float4 xv = *(const float4*)(xr + k0);
            const float* xs = (const float*)&xv;
#pragma unroll
            for (int kk = 0; kk < 4; kk++) {
                const float4* wg = (const float4*)(Wg + (size_t)(k0 + kk) * NUM_EXP);
                float4 w0 = wg[0], w1 = wg[1];
                float xk = xs[kk];
                acc[0] += xk * w0.x; acc[1] += xk * w0.y;
                acc[2] += xk * w0.z; acc[3] += xk * w0.w;
                acc[4] += xk * w1.x; acc[5] += xk * w1.y;
                acc[6] += xk * w1.z; acc[7] += xk * w1.w;
            }
        }
#pragma unroll
        for (int off = 16; off; off >>= 1)
#pragma unroll
            for (int e = 0; e < NUM_EXP; e++)
                acc[e] += __shfl_xor_sync(0xFFFFFFFFu, acc[e], off);
        if (lane == 0) {
            float v[NUM_EXP];
#pragma unroll
            for (int e = 0; e < NUM_EXP; e++) v[e] = acc[e] + bg[e];
            int i1 = 0;
#pragma unroll
            for (int e = 1; e < NUM_EXP; e++) if (v[e] > v[i1]) i1 = e;
            int i2 = -1;
#pragma unroll
            for (int e = 0; e < NUM_EXP; e++)
                if (e != i1 && (i2 < 0 || v[e] > v[i2])) i2 = e;
            float e2 = expf(v[i2] - v[i1]);
            float g1 = 1.f / (1.f + e2), g2 = e2 / (1.f + e2);
#pragma unroll
            for (int e = 0; e < NUM_EXP; e++) g_gates[gwarp * NUM_EXP + e] = 0.f;
            g_gates[gwarp * NUM_EXP + i1] = g1;
            g_gates[gwarp * NUM_EXP + i2] = g2;
            g_topi[gwarp * TOPK + 0] = i1;
            g_topi[gwarp * TOPK + 1] = i2;
            g_pairExpert[gwarp * TOPK + 0] = i1;
            g_pairExpert[gwarp * TOPK + 1] = i2;
            g_pairGate[gwarp * TOPK + 0] = g1;
            g_pairGate[gwarp * TOPK + 1] = g2;
            atomicAdd(&g_counts[i1], 1);
            atomicAdd(&g_counts[i2], 1);
        }

        for (size_t i = tid0; i < (size_t)BATCH * D_MODEL / 4; i += nthr) {
            float4 v = ((const float4*)x)[i];
            ((__half2*)g_xH)[i * 2]     = __floats2half2_rn(v.x, v.y);
            ((__half2*)g_xH)[i * 2 + 1] = __floats2half2_rn(v.z, v.w);
        }

        __syncthreads();
        if (tid == 0) {
            __threadfence();
            unsigned ticket = atomicAdd(&g_done, 1u);
            if (ticket == RTR_BLOCKS - 1) {
                int base = 0;
#pragma unroll
                for (int e = 0; e < NUM_EXP; e++) {
                    g_segbase[e] = base;
                    g_cursor[e]  = base;
                    base += ((g_counts[e] + 127) >> 7) << 7;
                }
                g_segbase[NUM_EXP] = base;
                g_done = 0;
                __threadfence();
            }
        }
        return;
    }

    // W1 [e][k=1024][n=4096] -> W1T [e][n][k] fp16
    const int tx = tid & 63, ty4 = tid >> 6;
    int idx = bid - RTR_BLOCKS;
    int e  = idx >> 10;
    int tt = idx & 1023;
    int kB = (tt & 15) * 64;
    int nB = (tt >> 4) * 64;
    const float* src = W1 + (size_t)e * D_MODEL * HIDDEN;
    __half* dst = g_W1T + (size_t)e * HIDDEN * D_MODEL;
#pragma unroll
    for (int i = 0; i < 16; i++) {
        int r = ty4 + i * 4;
        t[r][tx] = src[(size_t)(kB + r) * HIDDEN + nB + tx];
    }
    __syncthreads();
#pragma unroll
    for (int i = 0; i < 16; i++) {
        int r = ty4 + i * 4;
        dst[(size_t)(nB + r) * D_MODEL + kB + tx] = __float2half_rn(t[tx][r]);
    }
}

// ---------------- L2: scatter (standalone, R14-proven) ----------------------
__global__ void scatter_kernel() {
    int p = blockIdx.x * blockDim.x + threadIdx.x;
    if (p >= NPAIR) return;
    int e = g_pairExpert[p];
    int pos = atomicAdd(&g_cursor[e], 1);
    g_permToken[pos] = p >> 1;
    g_permPair[pos]  = p;
    g_permGate[pos]  = g_pairGate[p];
}

// ---------------- fp16 mma GEMMs (R14-proven) -------------------------------
#define ROWB      144
#define A_BYTES   (128 * ROWB)
#define B_BYTES   (128 * ROWB)
#define STAGE_B   (A_BYTES + B_BYTES)
#define NSTAGE    3
#define SMEM_TOT  (NSTAGE * STAGE_B)               // 110592

__device__ __forceinline__ void issue_chunk(
    uint32_t aDst, uint32_t bDst,
    const __half* aSrc, uint32_t aSz, const __half* bSrc, int kt)
{
#pragma unroll
    for (int j = 0; j < 4; j++)
        CPG16_SZ(aDst + j * 16, aSrc + kt + j * 8, aSz);
#pragma unroll
    for (int j = 0; j < 4; j++)
        CPG16(bDst + j * 16, bSrc + kt + j * 8);
    CPA_COMMIT();
}

__device__ __forceinline__ void mma_tile(uint32_t aAddr, uint32_t bAddr,
                                         float c[4][4][4]) {
#pragma unroll
    for (int ks = 0; ks < 4; ks++) {
        uint32_t a[4][4], b[2][4];
#pragma unroll
        for (int mi = 0; mi < 4; mi++)
            ldsm4(a[mi], aAddr + mi * (16 * ROWB) + ks * 32);
#pragma unroll
        for (int n2 = 0; n2 < 2; n2++)
            ldsm4(b[n2], bAddr + n2 * (16 * ROWB) + ks * 32);
#pragma unroll
        for (int mi = 0; mi < 4; mi++)
#pragma unroll
            for (int n2 = 0; n2 < 2; n2++) {
                mma_f16(c[mi][2 * n2],     a[mi], b[n2][0], b[n2][1]);
                mma_f16(c[mi][2 * n2 + 1], a[mi], b[n2][2], b[n2][3]);
            }
    }
}

__device__ __forceinline__ void gemm_mainloop(
    uint32_t aDst, uint32_t bDst,
    const __half* aSrc, uint32_t aSz, const __half* bSrc, int NIT,
    uint32_t aAddr, uint32_t bAddr, float c[4][4][4])
{
    issue_chunk(aDst, bDst, aSrc, aSz, bSrc, 0);
    issue_chunk(aDst + STAGE_B, bDst + STAGE_B, aSrc, aSz, bSrc, 64);
    int buf = 0, nxt = 2;
    for (int it = 0; it < NIT; ++it) {
        if (it + 1 < NIT) CPA_WAIT1(); else CPA_WAIT0();
        __syncthreads();
        if (it + 2 < NIT)
            issue_chunk(aDst + nxt * STAGE_B, bDst + nxt * STAGE_B,
                        aSrc, aSz, bSrc, (it + 2) * 64);
        mma_tile(aAddr + buf * STAGE_B, bAddr + buf * STAGE_B, c);
        buf = (buf == NSTAGE - 1) ? 0 : buf + 1;
        nxt = (nxt == NSTAGE - 1) ? 0 : nxt + 1;
    }
}

// gemm1 tiles in blocks [0, G1_BLOCKS); W2 transpose tiles after (fill tail).
// Transpose scratch lives in the DYNAMIC smem buffer (no extra static smem).
__global__ __launch_bounds__(256, 2)
void gemm1_fused(const float* __restrict__ b1, const float* __restrict__ W2) {
    extern __shared__ __align__(16) char smem[];
    const int tid = threadIdx.x;

    if (blockIdx.x >= G1_BLOCKS) {
        // ---- W2 [e][k=4096][n=1000] -> W2T [e][n=1024pad][k] fp16 ----------
        float (*t)[65] = (float(*)[65])smem;       // 64x65 floats in dyn smem
        const int tx = tid & 63, ty4 = tid >> 6;
        int idx = blockIdx.x - G1_BLOCKS;
        int e  = idx >> 10;
        int tt = idx & 1023;
        int kB = (tt & 63) * 64;
        int nB = (tt >> 6) * 64;
        const float* src = W2 + (size_t)e * HIDDEN * NUM_CLS;
        __half* dst = g_W2T + (size_t)e * N2PAD * HIDDEN;
        int n = nB + tx;
#pragma unroll
        for (int i = 0; i < 16; i++) {
            int r = ty4 + i * 4;
            t[r][tx] = (n < NUM_CLS) ? src[(size_t)(kB + r) * NUM_CLS + n] : 0.f;
        }
        __syncthreads();
#pragma unroll
        for (int i = 0; i < 16; i++) {
            int r = ty4 + i * 4;
            dst[(size_t)(nB + r) * HIDDEN + kB + tx] = __float2half_rn(t[tx][r]);
        }
        return;
    }

    // ---- gemm1 tile ---------------------------------------------------------
    const int wid = tid >> 5, lane = tid & 31;
    const int rowBase = (blockIdx.x % MAX_TILES) * 128;
    const int nBase   = (blockIdx.x / MAX_TILES) * 128;
    if (rowBase >= g_segbase[NUM_EXP]) return;
    int expert = 0;
#pragma unroll
    for (int i = 1; i < NUM_EXP; i++) if (g_segbase[i] <= rowBase) expert = i;

    uint32_t sb = smem_u32(smem);
    const int cr = tid >> 1, co = (tid & 1) * 32;
    uint32_t aDst = sb + cr * ROWB + co * 2;
    uint32_t bDst = sb + A_BYTES + cr * ROWB + co * 2;

    const int tok = g_permToken[rowBase + cr];
    const __half* aSrc = g_xH + (size_t)(tok < 0 ? 0 : tok) * D_MODEL + co;
    uint32_t aSz = tok < 0 ? 0u : 16u;
    const __half* bSrc = g_W1T + (size_t)expert * HIDDEN * D_MODEL
                       + (size_t)(nBase + cr) * D_MODEL + co;

    const int gid = lane >> 2, tig = lane & 3;
    const int wr = (wid >> 2) * 64, wc = (wid & 3) * 32;
    const int g8 = lane >> 3, r8 = lane & 7;
    uint32_t aAddr = sb + (wr + (g8 & 1) * 8 + r8) * ROWB + (g8 >> 1) * 16;
    uint32_t bAddr = sb + A_BYTES + (wc + (g8 >> 1) * 8 + r8) * ROWB + (g8 & 1) * 16;

    float c[4][4][4];
#pragma unroll
    for (int mi = 0; mi < 4; mi++)
#pragma unroll
        for (int ni = 0; ni < 4; ni++)
#pragma unroll
            for (int q = 0; q < 4; q++) c[mi][ni][q] = 0.f;

    gemm_mainloop(aDst, bDst, aSrc, aSz, bSrc, D_MODEL / 64, aAddr, bAddr, c);

    const float* bb = b1 + (size_t)expert * HIDDEN + nBase;
#pragma unroll
    for (int mi = 0; mi < 4; mi++) {
        int r0 = rowBase + wr + mi * 16 + gid;
#pragma unroll
        for (int ni = 0; ni < 4; ni++) {
            int col = wc + ni * 8 + tig * 2;
            float bias0 = __ldg(bb + col), bias1 = __ldg(bb + col + 1);
            __half2 v0 = __floats2half2_rn(gelu_exact(c[mi][ni][0] + bias0),
                                           gelu_exact(c[mi][ni][1] + bias1));
            __half2 v1 = __floats2half2_rn(gelu_exact(c[mi][ni][2] + bias0),
                                           gelu_exact(c[mi][ni][3] + bias1));
            *(__half2*)(g_h + (size_t)r0 * HIDDEN + nBase + col) = v0;
            *(__half2*)(g_h + (size_t)(r0 + 8) * HIDDEN + nBase + col) = v1;
        }
    }
}

// grid = (nTiles fast, rowTiles) for g_h L2 reuse.
__global__ __launch_bounds__(256, 2)
void gemm2_mma(const float* __restrict__ b2, float* __restrict__ out) {
    extern __shared__ __align__(16) char smem[];
    const int tid = threadIdx.x, wid = tid >> 5, lane = tid & 31;
    const int rowBase = blockIdx.y * 128, nBase = blockIdx.x * 128;
    if (rowBase >= g_segbase[NUM_EXP]) return;
    int expert = 0;
#pragma unroll
    for (int i = 1; i < NUM_EXP; i++) if (g_segbase[i] <= rowBase) expert = i;

    uint32_t sb = smem_u32(smem);
    const int cr = tid >> 1, co = (tid & 1) * 32;
    uint32_t aDst = sb + cr * ROWB + co * 2;
    uint32_t bDst = sb + A_BYTES + cr * ROWB + co * 2;

    const __half* aSrc = g_h + (size_t)(rowBase + cr) * HIDDEN + co;
    const __half* bSrc = g_W2T + (size_t)expert * N2PAD * HIDDEN
                       + (size_t)(nBase + cr) * HIDDEN + co;

    const int gid = lane >> 2, tig = lane & 3;
    const int wr = (wid >> 2) * 64, wc = (wid & 3) * 32;
    const int g8 = lane >> 3, r8 = lane & 7;
    uint32_t aAddr = sb + (wr + (g8 & 1) * 8 + r8) * ROWB + (g8 >> 1) * 16;
    uint32_t bAddr = sb + A_BYTES + (wc + (g8 >> 1) * 8 + r8) * ROWB + (g8 & 1) * 16;

    float c[4][4][4];
#pragma unroll
    for (int mi = 0; mi < 4; mi++)
#pragma unroll
        for (int ni = 0; ni < 4; ni++)
#pragma unroll
            for (int q = 0; q < 4; q++) c[mi][ni][q] = 0.f;

    gemm_mainloop(aDst, bDst, aSrc, 16u, bSrc, HIDDEN / 64, aAddr, bAddr, c);

    const float* bb = b2 + (size_t)expert * NUM_CLS;
#pragma unroll
    for (int mi = 0; mi < 4; mi++) {
        int r0 = rowBase + wr + mi * 16 + gid;
#pragma unroll
        for (int half = 0; half < 2; half++) {
            int r = r0 + half * 8;
            int pair = g_permPair[r];
            if (pair < 0) continue;
            float gate = g_permGate[r];
            float* orow = out + (size_t)(pair >> 1) * NUM_CLS;
#pragma unroll
            for (int ni = 0; ni < 4; ni++) {
                int col = nBase + wc + ni * 8 + tig * 2;
                if (col < NUM_CLS)
                    atomicAdd(orow + col, gate * (c[mi][ni][half * 2 + 0] + __ldg(bb + col)));
                if (col + 1 < NUM_CLS)
                    atomicAdd(orow + col + 1, gate * (c[mi][ni][half * 2 + 1] + __ldg(bb + col + 1)));
            }
        }
    }
}

// ---------------- tail -------------------------------------------------------
__global__ void tail_kernel(float* __restrict__ out, int out_size) {
    int i = blockIdx.x * blockDim.x + threadIdx.x;
    const int OUT0 = BATCH * NUM_CLS;
    if (out_size >= OUT0 + BATCH * NUM_EXP) {
        if (i < BATCH * NUM_EXP)
            out[OUT0 + i] = g_gates[i];
        if (out_size >= OUT0 + BATCH * NUM_EXP + BATCH * TOPK && i < BATCH * TOPK)
            out[OUT0 + BATCH * NUM_EXP + i] = (float)g_topi[i];
    }
}

// ---------------------------------------------------------------------------
extern "C" void kernel_launch(void* const* d_in, const int* in_sizes, int n_in,
                              void* d_out, int out_size) {
    const float* x  = (const float*)d_in[0];
    const float* Wg = (const float*)d_in[1];
    const float* bg = (const float*)d_in[2];
    const float* W1 = (const float*)d_in[3];
    const float* b1 = (const float*)d_in[4];
    const float* W2 = (const float*)d_in[5];
    const float* b2 = (const float*)d_in[6];
    float* out = (float*)d_out;

    cudaFuncSetAttribute(gemm1_fused, cudaFuncAttributeMaxDynamicSharedMemorySize, SMEM_TOT);
    cudaFuncSetAttribute(gemm2_mma, cudaFuncAttributeMaxDynamicSharedMemorySize, SMEM_TOT);

    // ncu profiles launch index 4 -> gemm2_mma.
    cudaMemsetAsync(d_out, 0, (size_t)out_size * sizeof(float));             // 0
    prep_all<<<PREP_BLOCKS, 256>>>(x, Wg, bg, W1);                           // 1
    scatter_kernel<<<(NPAIR + 255) / 256, 256>>>();                          // 2
    gemm1_fused<<<G1_BLOCKS + T2_BLOCKS, 256, SMEM_TOT>>>(b1, W2);           // 3
    gemm2_mma<<<dim3(N2PAD / 128, MAX_TILES), 256, SMEM_TOT>>>(b2, out);     // 4 <- ncu
    tail_kernel<<<(BATCH * NUM_EXP + 255) / 256, 256>>>(out, out_size);      // 5
}